// round 8
// baseline (speedup 1.0000x reference)
#include <cuda_runtime.h>

// DepthToSpace, block_size=2
// in : x[16, 256, 128, 128] fp32
// out: y[16,  64, 256, 256] fp32
// out[b, dd, 2h+i, 2w+k] = x[b, i*128 + k*64 + dd, h, w]
//
// Per-thread: two adjacent input rows (h = 2*h2, 2*h2+1) of channel pair
// (c0 = i*128+dd, c1 = c0+64), one float4 each -> four output float4s across
// two output rows (oh = 4*h2+i and 4*h2+2+i).
// Per-warp: reads 1KB contiguous from c0, 1KB from c1; writes two full 1KB
// output rows. 4x LDG.128 + 4x STG.128 per thread, all coalesced, evict-first.

#define B_   16
#define C_   256
#define H_   128
#define W_   128
#define D_   64          // out channels
#define OH_  256
#define WF4_ 32          // input row width in float4 (128/4)

// distance between channel c and c+64 in float4 units
#define C64_STRIDE_F4 (64 * H_ * WF4_)

__global__ __launch_bounds__(256) void d2s_kernel(
    const float4* __restrict__ x4, float4* __restrict__ out4)
{
    const int tid = blockIdx.x * blockDim.x + threadIdx.x;   // [0, 16*64*2*64*32)

    const int q   = tid & (WF4_ - 1);     // float4 index within input row
    int t         = tid >> 5;
    const int h2  = t & 63;               // input row pair index (h = 2*h2, 2*h2+1)
    t >>= 6;
    const int i   = t & 1;                // height-block bit
    const int bd  = t >> 1;               // b*64 + dd
    const int dd  = bd & (D_ - 1);
    const int b   = bd >> 6;

    const int c0 = i * 128 + dd;          // k=0 channel; k=1 channel is c0+64
    const int h  = 2 * h2;

    // float4 index of x[b, c0, h, 4q]
    const int base = (( (b * C_ + c0) * H_ + h ) * WF4_) + q;

    const float4 a0 = __ldcs(&x4[base]);                        // c0, row h
    const float4 b0 = __ldcs(&x4[base + WF4_]);                 // c0, row h+1
    const float4 a1 = __ldcs(&x4[base + C64_STRIDE_F4]);        // c1, row h
    const float4 b1 = __ldcs(&x4[base + C64_STRIDE_F4 + WF4_]); // c1, row h+1

    // output rows: oh0 = 4*h2 + i (from h), oh1 = oh0 + 2 (from h+1)
    const int oh0 = 4 * h2 + i;
    const int orow0 = (bd * OH_ + oh0) * 64 + 2 * q;   // float4 units
    const int orow1 = orow0 + 2 * 64;                  // oh0 + 2

    __stcs(&out4[orow0],     make_float4(a0.x, a1.x, a0.y, a1.y));
    __stcs(&out4[orow0 + 1], make_float4(a0.z, a1.z, a0.w, a1.w));
    __stcs(&out4[orow1],     make_float4(b0.x, b1.x, b0.y, b1.y));
    __stcs(&out4[orow1 + 1], make_float4(b0.z, b1.z, b0.w, b1.w));
}

extern "C" void kernel_launch(void* const* d_in, const int* in_sizes, int n_in,
                              void* d_out, int out_size)
{
    const float4* x4 = (const float4*)d_in[0];
    float4* out4 = (float4*)d_out;

    const unsigned total_threads = B_ * D_ * 2 * 64 * WF4_;   // 4,194,304
    d2s_kernel<<<total_threads / 256u, 256>>>(x4, out4);
}